// round 5
// baseline (speedup 1.0000x reference)
#include <cuda_runtime.h>
#include <cuda_bf16.h>

// warp3D trilinear backward-warp, shared-memory tiled, 2 CTAs/SM.
// out[b,c,d,h,w] = trilinear(I[b,c], (w,h,d) + flow[b,{0,1,2},d,h,w])
// Matches reference math exactly (clamp-order + clamped-x1 weights).
//
// Each CTA caches a 24x24x24 float2 tile (both channels interleaved) of I
// covering its 16x16x16 output tile plus a +-4 halo -> 112.5 KB smem, so TWO
// CTAs co-reside per SM and overlap tile-load with compute. The 8 corner
// gathers per point become 8 x LDS.64. Out-of-halo samples (P ~ 6e-5) take a
// bit-identical global-gather fallback.

#define BB 2
#define CC 2
#define DD 160
#define HH 192
#define WW 224

static constexpr int HW  = HH * WW;          // 43008
static constexpr int DHW = DD * HW;          // 6,881,280

static constexpr int TD = 16, TH = 16, TW = 16;   // output tile
static constexpr int R  = 4;                      // halo radius
static constexpr int DIN = TD + 2 * R;            // 24
static constexpr int HIN = TH + 2 * R;            // 24
static constexpr int WIN = TW + 2 * R;            // 24
static constexpr int STR = WIN + 1;               // 25 (odd -> rows decorrelate banks)
static constexpr int NROWS = DIN * HIN;           // 576
static constexpr int SMEM_BYTES = NROWS * STR * (int)sizeof(float2); // 115200

static constexpr int NTHREADS = 512;
static constexpr int NWARPS   = NTHREADS / 32;    // 16

__global__ __launch_bounds__(NTHREADS, 2)
void warp3d_tiled2(const float* __restrict__ I,
                   const float* __restrict__ flow,
                   float* __restrict__ out)
{
    extern __shared__ float2 tile[];

    const int tid  = threadIdx.x;
    const int wid  = tid >> 5;
    const int lane = tid & 31;

    const int wbase = blockIdx.x * TW;
    const int hbase = blockIdx.y * TH;
    const int zb    = blockIdx.z;               // 0 .. (DD/TD)*BB - 1
    const int b     = zb / (DD / TD);
    const int dbase = (zb % (DD / TD)) * TD;

    const float* __restrict__ I0 = I + (size_t)b * CC * DHW;  // channel 0
    const float* __restrict__ I1 = I0 + DHW;                  // channel 1

    const int z0g = dbase - R;
    const int y0g = hbase - R;
    const int x0g = wbase - R;

    // ---- Stage 1: cooperative tile load, one (iz,iy) row per warp step ----
    // 576 rows / 16 warps = 36 steps; lanes 0..23 each load one float2.
    if (lane < WIN) {
        const int gx = min(max(x0g + lane, 0), WW - 1);
        #pragma unroll 4
        for (int r = wid; r < NROWS; r += NWARPS) {
            int iz = r / HIN;
            int iy = r - iz * HIN;
            int gz = min(max(z0g + iz, 0), DD - 1);
            int gy = min(max(y0g + iy, 0), HH - 1);
            int go = gz * HW + gy * WW + gx;
            tile[r * STR + lane] = make_float2(I0[go], I1[go]);
        }
    }

    // ---- Stage 2: batch flow loads for this thread's 8 points ----
    const int px   = tid & 15;                  // w within tile
    const int py   = (tid >> 4) & 15;           // h within tile
    const int dpar = tid >> 8;                  // 0/1: d parity slot
    const int w    = wbase + px;
    const int h    = hbase + py;

    const float* __restrict__ fb = flow + (size_t)b * 3 * DHW;
    const int s_base = h * WW + w;

    float fxs[8], fys[8], fzs[8];
    #pragma unroll
    for (int k = 0; k < 8; k++) {
        int d = dbase + (k << 1) + dpar;
        int s = d * HW + s_base;
        fxs[k] = fb[s];
        fys[k] = fb[DHW + s];
        fzs[k] = fb[2 * DHW + s];
    }

    __syncthreads();

    float* __restrict__ ob = out + (size_t)b * CC * DHW;

    // ---- Stage 3: compute 8 output points per thread ----
    #pragma unroll 4
    for (int k = 0; k < 8; k++) {
        const int d = dbase + (k << 1) + dpar;
        const int s = d * HW + s_base;

        float x = fxs[k] + (float)w;
        float y = fys[k] + (float)h;
        float z = fzs[k] + (float)d;

        int x0r = (int)floorf(x);
        int y0r = (int)floorf(y);
        int z0r = (int)floorf(z);

        int x1 = min(max(x0r + 1, 0), WW - 1);
        int y1 = min(max(y0r + 1, 0), HH - 1);
        int z1 = min(max(z0r + 1, 0), DD - 1);
        int x0 = min(max(x0r, 0), WW - 1);
        int y0 = min(max(y0r, 0), HH - 1);
        int z0 = min(max(z0r, 0), DD - 1);

        // Weights from CLAMPED upper corner (matches reference)
        float dx = (float)x1 - x;
        float dy = (float)y1 - y;
        float dz = (float)z1 - z;
        float ex = 1.0f - dx;
        float ey = 1.0f - dy;
        float ez = 1.0f - dz;

        float wa = dz * dx * dy;   // (z0, y0, x0)
        float wb = dz * dx * ey;   // (z0, y1, x0)
        float wc = dz * ex * dy;   // (z0, y0, x1)
        float wd = dz * ex * ey;   // (z0, y1, x1)
        float we = ez * dx * dy;   // (z1, y0, x0)
        float wf = ez * dx * ey;   // (z1, y1, x0)
        float wg = ez * ex * dy;   // (z1, y0, x1)
        float wh = ez * ex * ey;   // (z1, y1, x1)

        int tx0 = x0 - x0g, tx1 = x1 - x0g;
        int ty0 = y0 - y0g, ty1 = y1 - y0g;
        int tz0 = z0 - z0g, tz1 = z1 - z0g;

        bool inside = (tx0 >= 0) & (tx1 < WIN)
                    & (ty0 >= 0) & (ty1 < HIN)
                    & (tz0 >= 0) & (tz1 < DIN);

        float acc0, acc1;

        if (inside) {
            int r00 = (tz0 * HIN + ty0) * STR;
            int r01 = (tz0 * HIN + ty1) * STR;
            int r10 = (tz1 * HIN + ty0) * STR;
            int r11 = (tz1 * HIN + ty1) * STR;

            float2 va = tile[r00 + tx0];
            float2 vb = tile[r01 + tx0];
            float2 vc = tile[r00 + tx1];
            float2 vd = tile[r01 + tx1];
            float2 ve = tile[r10 + tx0];
            float2 vf = tile[r11 + tx0];
            float2 vg = tile[r10 + tx1];
            float2 vh = tile[r11 + tx1];

            acc0 = wa * va.x;
            acc0 = fmaf(wb, vb.x, acc0);
            acc0 = fmaf(wc, vc.x, acc0);
            acc0 = fmaf(wd, vd.x, acc0);
            acc0 = fmaf(we, ve.x, acc0);
            acc0 = fmaf(wf, vf.x, acc0);
            acc0 = fmaf(wg, vg.x, acc0);
            acc0 = fmaf(wh, vh.x, acc0);

            acc1 = wa * va.y;
            acc1 = fmaf(wb, vb.y, acc1);
            acc1 = fmaf(wc, vc.y, acc1);
            acc1 = fmaf(wd, vd.y, acc1);
            acc1 = fmaf(we, ve.y, acc1);
            acc1 = fmaf(wf, vf.y, acc1);
            acc1 = fmaf(wg, vg.y, acc1);
            acc1 = fmaf(wh, vh.y, acc1);
        } else {
            // Rare fallback: displacement exceeded halo -> direct global gather
            int o000 = z0 * HW + y0 * WW + x0;
            int o010 = z0 * HW + y1 * WW + x0;
            int o001 = z0 * HW + y0 * WW + x1;
            int o011 = z0 * HW + y1 * WW + x1;
            int o100 = z1 * HW + y0 * WW + x0;
            int o110 = z1 * HW + y1 * WW + x0;
            int o101 = z1 * HW + y0 * WW + x1;
            int o111 = z1 * HW + y1 * WW + x1;

            acc0 = wa * I0[o000];
            acc0 = fmaf(wb, I0[o010], acc0);
            acc0 = fmaf(wc, I0[o001], acc0);
            acc0 = fmaf(wd, I0[o011], acc0);
            acc0 = fmaf(we, I0[o100], acc0);
            acc0 = fmaf(wf, I0[o110], acc0);
            acc0 = fmaf(wg, I0[o101], acc0);
            acc0 = fmaf(wh, I0[o111], acc0);

            acc1 = wa * I1[o000];
            acc1 = fmaf(wb, I1[o010], acc1);
            acc1 = fmaf(wc, I1[o001], acc1);
            acc1 = fmaf(wd, I1[o011], acc1);
            acc1 = fmaf(we, I1[o100], acc1);
            acc1 = fmaf(wf, I1[o110], acc1);
            acc1 = fmaf(wg, I1[o101], acc1);
            acc1 = fmaf(wh, I1[o111], acc1);
        }

        ob[s]       = acc0;
        ob[DHW + s] = acc1;
    }
}

extern "C" void kernel_launch(void* const* d_in, const int* in_sizes, int n_in,
                              void* d_out, int out_size)
{
    const float* I    = (const float*)d_in[0];
    const float* flow = (const float*)d_in[1];
    float* out        = (float*)d_out;

    // One-time config on the first (non-captured) correctness call; device
    // work per call is identical.
    static bool smem_cfg_done = false;
    if (!smem_cfg_done) {
        cudaFuncSetAttribute(warp3d_tiled2,
                             cudaFuncAttributeMaxDynamicSharedMemorySize,
                             SMEM_BYTES);
        smem_cfg_done = true;
    }

    dim3 grid(WW / TW, HH / TH, (DD / TD) * BB);   // 14 x 12 x 20
    warp3d_tiled2<<<grid, NTHREADS, SMEM_BYTES>>>(I, flow, out);
}

// round 6
// speedup vs baseline: 1.1025x; 1.1025x over previous
#include <cuda_runtime.h>
#include <cuda_bf16.h>

// warp3D trilinear backward-warp, two-phase:
//  1) interleave_kernel: build channel-interleaved copy Ipair[b][z][y][x]=(c0,c1)
//     (perfectly coalesced streaming pass into __device__ scratch).
//  2) warp3d_pair: per output point, 8 x 8B float2 gathers (both channels per
//     load) instead of 16 x 4B -> half the L1 gather wavefronts of the naive
//     kernel, which ncu showed to be the binding pipe (L1tex = 87%).
// Math matches reference exactly (clamp-order + clamped-x1 weights).

#define BB 2
#define CC 2
#define DD 160
#define HH 192
#define WW 224

static constexpr int HW  = HH * WW;          // 43008
static constexpr int DHW = DD * HW;          // 6,881,280
static constexpr int NPAIR = BB * DHW;       // 13,762,560 float2 elements

// 110 MB channel-interleaved scratch (static __device__ -> no runtime alloc)
__device__ float2 g_pair[NPAIR];

// ---------------- Phase 1: planar -> interleaved ----------------
// Processes 4 voxels per thread with float4 loads/stores.
static constexpr int IV_THREADS = 256;
static constexpr int IV_TOTAL   = NPAIR / 4;           // 3,440,640

__global__ __launch_bounds__(IV_THREADS)
void interleave_kernel(const float* __restrict__ I)
{
    int i = blockIdx.x * IV_THREADS + threadIdx.x;
    if (i >= IV_TOTAL) return;
    int v = i << 2;                    // first voxel index (global, b-major)
    int b = v / DHW;
    int s = v - b * DHW;

    const float4 a = *(const float4*)(I + (size_t)b * CC * DHW + s);        // c0
    const float4 c = *(const float4*)(I + (size_t)b * CC * DHW + DHW + s);  // c1

    float4* dst = (float4*)(g_pair + v);
    dst[0] = make_float4(a.x, c.x, a.y, c.y);
    dst[1] = make_float4(a.z, c.z, a.w, c.w);
}

// ---------------- Phase 2: gather/interpolate ----------------
// Block = one x-row (224 threads = 7 warps); blockIdx = (h, d, b).
// No div/mod anywhere; 3 flow loads + 8 float2 gathers, all independent.
__global__ __launch_bounds__(WW)
void warp3d_pair(const float* __restrict__ flow,
                 float* __restrict__ out)
{
    const int w = threadIdx.x;
    const int h = blockIdx.x;
    const int d = blockIdx.y;
    const int b = blockIdx.z;

    const int s = d * HW + h * WW + w;

    const float* __restrict__ fb = flow + (size_t)b * 3 * DHW;
    float x = fb[s]           + (float)w;
    float y = fb[s + DHW]     + (float)h;
    float z = fb[s + 2 * DHW] + (float)d;

    int x0r = (int)floorf(x);
    int y0r = (int)floorf(y);
    int z0r = (int)floorf(z);

    int x1 = min(max(x0r + 1, 0), WW - 1);
    int y1 = min(max(y0r + 1, 0), HH - 1);
    int z1 = min(max(z0r + 1, 0), DD - 1);
    int x0 = min(max(x0r, 0), WW - 1);
    int y0 = min(max(y0r, 0), HH - 1);
    int z0 = min(max(z0r, 0), DD - 1);

    // Weights from CLAMPED upper corner (matches reference)
    float dx = (float)x1 - x;
    float dy = (float)y1 - y;
    float dz = (float)z1 - z;
    float ex = 1.0f - dx;
    float ey = 1.0f - dy;
    float ez = 1.0f - dz;

    float wa = dz * dx * dy;   // (z0, y0, x0)
    float wb = dz * dx * ey;   // (z0, y1, x0)
    float wc = dz * ex * dy;   // (z0, y0, x1)
    float wd = dz * ex * ey;   // (z0, y1, x1)
    float we = ez * dx * dy;   // (z1, y0, x0)
    float wf = ez * dx * ey;   // (z1, y1, x0)
    float wg = ez * ex * dy;   // (z1, y0, x1)
    float wh = ez * ex * ey;   // (z1, y1, x1)

    const float2* __restrict__ P = g_pair + (size_t)b * DHW;

    int r00 = z0 * HW + y0 * WW;
    int r01 = z0 * HW + y1 * WW;
    int r10 = z1 * HW + y0 * WW;
    int r11 = z1 * HW + y1 * WW;

    float2 va = P[r00 + x0];
    float2 vb = P[r01 + x0];
    float2 vc = P[r00 + x1];
    float2 vd = P[r01 + x1];
    float2 ve = P[r10 + x0];
    float2 vf = P[r11 + x0];
    float2 vg = P[r10 + x1];
    float2 vh = P[r11 + x1];

    float acc0 = wa * va.x;
    acc0 = fmaf(wb, vb.x, acc0);
    acc0 = fmaf(wc, vc.x, acc0);
    acc0 = fmaf(wd, vd.x, acc0);
    acc0 = fmaf(we, ve.x, acc0);
    acc0 = fmaf(wf, vf.x, acc0);
    acc0 = fmaf(wg, vg.x, acc0);
    acc0 = fmaf(wh, vh.x, acc0);

    float acc1 = wa * va.y;
    acc1 = fmaf(wb, vb.y, acc1);
    acc1 = fmaf(wc, vc.y, acc1);
    acc1 = fmaf(wd, vd.y, acc1);
    acc1 = fmaf(we, ve.y, acc1);
    acc1 = fmaf(wf, vf.y, acc1);
    acc1 = fmaf(wg, vg.y, acc1);
    acc1 = fmaf(wh, vh.y, acc1);

    float* __restrict__ ob = out + (size_t)b * CC * DHW;
    ob[s]       = acc0;
    ob[s + DHW] = acc1;
}

extern "C" void kernel_launch(void* const* d_in, const int* in_sizes, int n_in,
                              void* d_out, int out_size)
{
    const float* I    = (const float*)d_in[0];
    const float* flow = (const float*)d_in[1];
    float* out        = (float*)d_out;

    interleave_kernel<<<(IV_TOTAL + IV_THREADS - 1) / IV_THREADS, IV_THREADS>>>(I);

    dim3 grid(HH, DD, BB);             // block = one x-row of 224 threads
    warp3d_pair<<<grid, WW>>>(flow, out);
}